// round 4
// baseline (speedup 1.0000x reference)
#include <cuda_runtime.h>
#include <cuda_bf16.h>
#include <cstdint>

#define NUM_USERS 100000
#define NUM_ITEMS 100000
#define N_TOTAL   200000
#define DIM       64
#define E_EDGES   3200000
#define SCAN_CHUNK 1024
#define SCAN_NBLK  ((N_TOTAL + SCAN_CHUNK - 1) / SCAN_CHUNK)   // 196

typedef unsigned long long ull;

// ---------------- scratch (device globals: no allocation allowed) ----------
__device__ float g_agg [N_TOTAL * DIM];   // aggregated (x + scatter) rows
__device__ float g_h   [N_TOTAL * DIM];   // layer-1 output
__device__ int2  g_esrt [E_EDGES];        // dst-sorted: {src, w_bits}
__device__ int   g_cnt [N_TOTAL];
__device__ int   g_off [N_TOTAL];
__device__ int   g_cur [N_TOTAL];
__device__ int   g_bsum[SCAN_NBLK];
__device__ int   g_is64;

// ---------------- packed f32x2 FMA (SASS FFMA2; PTX-only pattern) ----------
__device__ __forceinline__ ull ffma2(ull a, ull b, ull c) {
    ull d;
    asm("fma.rn.f32x2 %0, %1, %2, %3;" : "=l"(d) : "l"(a), "l"(b), "l"(c));
    return d;
}

// ---------------- detect index dtype (int64 vs int32) ----------------------
__global__ void detect_kernel(const long long* __restrict__ ei) {
    if (threadIdx.x == 0) {
        int ok = 1;
        #pragma unroll 1
        for (int i = 0; i < 64; i++) {
            long long v = ei[i];
            if (v < 0 || v >= (long long)N_TOTAL) { ok = 0; break; }
        }
        g_is64 = ok;
    }
}

// ---------------- histogram of dst (reads only dst half of edge_index) -----
__global__ void count_kernel(const void* __restrict__ ei) {
    int i = blockIdx.x * blockDim.x + threadIdx.x;
    if (i >= E_EDGES) return;
    int t;
    if (g_is64) t = (int)((const long long*)ei)[E_EDGES + i];
    else        t = ((const int*)ei)[E_EDGES + i];
    atomicAdd(&g_cnt[t], 1);
}

// ---------------- 3-phase exclusive scan of g_cnt -> g_off -----------------
__global__ void __launch_bounds__(SCAN_CHUNK) scan1_kernel() {
    __shared__ int sm[SCAN_CHUNK];
    int t = threadIdx.x;
    int i = blockIdx.x * SCAN_CHUNK + t;
    int v = (i < N_TOTAL) ? g_cnt[i] : 0;
    sm[t] = v;
    __syncthreads();
    for (int d = 1; d < SCAN_CHUNK; d <<= 1) {
        int a = (t >= d) ? sm[t - d] : 0;
        __syncthreads();
        sm[t] += a;
        __syncthreads();
    }
    if (i < N_TOTAL) g_off[i] = sm[t] - v;       // exclusive
    if (t == SCAN_CHUNK - 1) g_bsum[blockIdx.x] = sm[t];
}

__global__ void scan2_kernel() {
    __shared__ int sm[256];
    int t = threadIdx.x;
    int v = (t < SCAN_NBLK) ? g_bsum[t] : 0;
    sm[t] = v;
    __syncthreads();
    for (int d = 1; d < 256; d <<= 1) {
        int a = (t >= d) ? sm[t - d] : 0;
        __syncthreads();
        sm[t] += a;
        __syncthreads();
    }
    if (t < SCAN_NBLK) g_bsum[t] = sm[t] - v;    // exclusive
}

__global__ void scan3_kernel() {
    int i = blockIdx.x * blockDim.x + threadIdx.x;
    if (i >= N_TOTAL) return;
    int o = g_off[i] + g_bsum[i >> 10];
    g_off[i] = o;
    g_cur[i] = o;
}

// ---------------- placement: dst-sorted edge list from raw inputs ----------
__global__ void place_kernel(const void* __restrict__ ei,
                             const float* __restrict__ w) {
    int i = blockIdx.x * blockDim.x + threadIdx.x;
    if (i >= E_EDGES) return;
    int s, t;
    if (g_is64) {
        const long long* p = (const long long*)ei;
        s = (int)p[i];
        t = (int)p[E_EDGES + i];
    } else {
        const int* p = (const int*)ei;
        s = p[i];
        t = p[E_EDGES + i];
    }
    int pos = atomicAdd(&g_cur[t], 1);
    g_esrt[pos] = make_int2(s, __float_as_int(w[i]));
}

// ---------------- segmented aggregation: out[n] = x[n] + sum w*x[src] ------
// One warp per dst node; float2 per lane covers the 64-wide row.
// x is addressed through two bases (ue/ie split for layer 1; both=h layer 2).
__global__ void __launch_bounds__(256) aggregate_kernel(
        const float2* __restrict__ p0, const float2* __restrict__ p1,
        float2* __restrict__ out) {
    int warp = (blockIdx.x * blockDim.x + threadIdx.x) >> 5;
    int lane = threadIdx.x & 31;
    if (warp >= N_TOTAL) return;

    int start = g_off[warp];
    int cnt   = g_cnt[warp];

    const float2* rbase = (warp < NUM_USERS)
        ? p0 + (size_t)warp * 32
        : p1 + (size_t)(warp - NUM_USERS) * 32;
    float2 acc = rbase[lane];                    // residual term

    int e = start, end = start + cnt;
    for (; e + 1 < end; e += 2) {
        int2 d0 = g_esrt[e];
        int2 d1 = g_esrt[e + 1];
        const float2* b0 = (d0.x < NUM_USERS)
            ? p0 + (size_t)d0.x * 32 : p1 + (size_t)(d0.x - NUM_USERS) * 32;
        const float2* b1 = (d1.x < NUM_USERS)
            ? p0 + (size_t)d1.x * 32 : p1 + (size_t)(d1.x - NUM_USERS) * 32;
        float2 v0 = b0[lane];
        float2 v1 = b1[lane];
        float w0 = __int_as_float(d0.y);
        float w1 = __int_as_float(d1.y);
        acc.x += w0 * v0.x + w1 * v1.x;
        acc.y += w0 * v0.y + w1 * v1.y;
    }
    if (e < end) {
        int2 d0 = g_esrt[e];
        const float2* b0 = (d0.x < NUM_USERS)
            ? p0 + (size_t)d0.x * 32 : p1 + (size_t)(d0.x - NUM_USERS) * 32;
        float2 v0 = b0[lane];
        float w0 = __int_as_float(d0.y);
        acc.x += w0 * v0.x;
        acc.y += w0 * v0.y;
    }
    out[(size_t)warp * 32 + lane] = acc;
}

// ---------------- linear: out = 0.5 * in @ W + b ---------------------------
// 4 rows per warp, packed f32x2 accumulation over k-pairs.
// Smem W pre-paired: Ws2[j*64 + c] = {W[2j][c], W[2j+1][c]}.
__global__ void __launch_bounds__(256) linear_kernel(
        const float* __restrict__ in, const float* __restrict__ W,
        const float* __restrict__ b, float* __restrict__ out) {
    __shared__ ull Ws2[32 * 64];
    __shared__ float bs[DIM];
    for (int idx = threadIdx.x; idx < 32 * 64; idx += blockDim.x) {
        int j = idx >> 6, c = idx & 63;
        float2 p = make_float2(W[(2 * j) * DIM + c], W[(2 * j + 1) * DIM + c]);
        Ws2[idx] = *reinterpret_cast<ull*>(&p);
    }
    if (threadIdx.x < DIM) bs[threadIdx.x] = b[threadIdx.x];
    __syncthreads();

    int lane  = threadIdx.x & 31;
    int warp  = threadIdx.x >> 5;
    int gwarp = blockIdx.x * (blockDim.x >> 5) + warp;
    int nwarp = gridDim.x * (blockDim.x >> 5);

    union F4U { float4 f; ull u[2]; };

    for (int base = gwarp * 4; base < N_TOTAL; base += nwarp * 4) {
        const float4* r0 = reinterpret_cast<const float4*>(in + (size_t)(base + 0) * DIM);
        const float4* r1 = reinterpret_cast<const float4*>(in + (size_t)(base + 1) * DIM);
        const float4* r2 = reinterpret_cast<const float4*>(in + (size_t)(base + 2) * DIM);
        const float4* r3 = reinterpret_cast<const float4*>(in + (size_t)(base + 3) * DIM);

        ull a00 = 0, a01 = 0, a10 = 0, a11 = 0;
        ull a20 = 0, a21 = 0, a30 = 0, a31 = 0;

        #pragma unroll
        for (int jj = 0; jj < 16; jj++) {           // jj covers k-pairs 2jj, 2jj+1
            F4U v0, v1, v2, v3;
            v0.f = r0[jj]; v1.f = r1[jj]; v2.f = r2[jj]; v3.f = r3[jj];
            ull wA0 = Ws2[(2 * jj) * 64 + lane];
            ull wA1 = Ws2[(2 * jj) * 64 + 32 + lane];
            ull wB0 = Ws2[(2 * jj + 1) * 64 + lane];
            ull wB1 = Ws2[(2 * jj + 1) * 64 + 32 + lane];

            a00 = ffma2(v0.u[0], wA0, a00); a01 = ffma2(v0.u[0], wA1, a01);
            a10 = ffma2(v1.u[0], wA0, a10); a11 = ffma2(v1.u[0], wA1, a11);
            a20 = ffma2(v2.u[0], wA0, a20); a21 = ffma2(v2.u[0], wA1, a21);
            a30 = ffma2(v3.u[0], wA0, a30); a31 = ffma2(v3.u[0], wA1, a31);

            a00 = ffma2(v0.u[1], wB0, a00); a01 = ffma2(v0.u[1], wB1, a01);
            a10 = ffma2(v1.u[1], wB0, a10); a11 = ffma2(v1.u[1], wB1, a11);
            a20 = ffma2(v2.u[1], wB0, a20); a21 = ffma2(v2.u[1], wB1, a21);
            a30 = ffma2(v3.u[1], wB0, a30); a31 = ffma2(v3.u[1], wB1, a31);
        }

        float b0v = bs[lane], b1v = bs[32 + lane];
        float2 s;
        s = *reinterpret_cast<float2*>(&a00);
        out[(size_t)(base + 0) * DIM + lane]      = 0.5f * (s.x + s.y) + b0v;
        s = *reinterpret_cast<float2*>(&a01);
        out[(size_t)(base + 0) * DIM + 32 + lane] = 0.5f * (s.x + s.y) + b1v;
        s = *reinterpret_cast<float2*>(&a10);
        out[(size_t)(base + 1) * DIM + lane]      = 0.5f * (s.x + s.y) + b0v;
        s = *reinterpret_cast<float2*>(&a11);
        out[(size_t)(base + 1) * DIM + 32 + lane] = 0.5f * (s.x + s.y) + b1v;
        s = *reinterpret_cast<float2*>(&a20);
        out[(size_t)(base + 2) * DIM + lane]      = 0.5f * (s.x + s.y) + b0v;
        s = *reinterpret_cast<float2*>(&a21);
        out[(size_t)(base + 2) * DIM + 32 + lane] = 0.5f * (s.x + s.y) + b1v;
        s = *reinterpret_cast<float2*>(&a30);
        out[(size_t)(base + 3) * DIM + lane]      = 0.5f * (s.x + s.y) + b0v;
        s = *reinterpret_cast<float2*>(&a31);
        out[(size_t)(base + 3) * DIM + 32 + lane] = 0.5f * (s.x + s.y) + b1v;
    }
}

// ---------------- launch ----------------------------------------------------
extern "C" void kernel_launch(void* const* d_in, const int* in_sizes, int n_in,
                              void* d_out, int out_size) {
    const void*  ei = d_in[0];
    const float* ew = (const float*)d_in[1];
    const float* ue = (const float*)d_in[2];
    const float* ie = (const float*)d_in[3];
    const float* W1 = (const float*)d_in[4];
    const float* b1 = (const float*)d_in[5];
    const float* W2 = (const float*)d_in[6];
    const float* b2 = (const float*)d_in[7];
    float* out = (float*)d_out;

    float *pagg, *ph;
    int   *pcnt;
    cudaGetSymbolAddress((void**)&pagg, g_agg);
    cudaGetSymbolAddress((void**)&ph,   g_h);
    cudaGetSymbolAddress((void**)&pcnt, g_cnt);

    cudaMemsetAsync(pcnt, 0, N_TOTAL * sizeof(int));

    detect_kernel<<<1, 32>>>((const long long*)ei);

    count_kernel<<<(E_EDGES + 255) / 256, 256>>>(ei);

    scan1_kernel<<<SCAN_NBLK, SCAN_CHUNK>>>();
    scan2_kernel<<<1, 256>>>();
    scan3_kernel<<<(N_TOTAL + 255) / 256, 256>>>();

    place_kernel<<<(E_EDGES + 255) / 256, 256>>>(ei, ew);

    const int agg_blocks = (N_TOTAL * 32 + 255) / 256;   // 1 warp per node
    const int ln_blocks  = 1024;

    // Layer 1: aggregate straight out of ue/ie (no concat copy)
    aggregate_kernel<<<agg_blocks, 256>>>(
        (const float2*)ue, (const float2*)ie, (float2*)pagg);
    linear_kernel<<<ln_blocks, 256>>>(pagg, W1, b1, ph);

    // Layer 2: both bases point into h
    aggregate_kernel<<<agg_blocks, 256>>>(
        (const float2*)ph, (const float2*)(ph + (size_t)NUM_USERS * DIM),
        (float2*)pagg);
    linear_kernel<<<ln_blocks, 256>>>(pagg, W2, b2, out);
}

// round 5
// speedup vs baseline: 1.1508x; 1.1508x over previous
#include <cuda_runtime.h>
#include <cuda_bf16.h>
#include <cstdint>

#define NUM_USERS 100000
#define NUM_ITEMS 100000
#define N_TOTAL   200000
#define DIM       64
#define E_EDGES   3200000
#define SCAN_CHUNK 1024
#define SCAN_NBLK  ((N_TOTAL + SCAN_CHUNK - 1) / SCAN_CHUNK)   // 196

typedef unsigned long long ull;

// ---------------- scratch (device globals: no allocation allowed) ----------
__device__ float g_x   [N_TOTAL * DIM];   // layer-0 input x (concat copy)
__device__ float g_agg [N_TOTAL * DIM];   // aggregated (x + scatter) rows
__device__ float g_h   [N_TOTAL * DIM];   // layer-1 output
__device__ int2  g_esrt [E_EDGES];        // dst-sorted: {src, w_bits}
__device__ int   g_cnt [N_TOTAL];
__device__ int   g_off [N_TOTAL];
__device__ int   g_cur [N_TOTAL];
__device__ int   g_bsum[SCAN_NBLK];
__device__ int   g_is64;

// ---------------- packed f32x2 FMA (SASS FFMA2; PTX-only pattern) ----------
__device__ __forceinline__ ull ffma2(ull a, ull b, ull c) {
    ull d;
    asm("fma.rn.f32x2 %0, %1, %2, %3;" : "=l"(d) : "l"(a), "l"(b), "l"(c));
    return d;
}

// ---------------- detect index dtype (int64 vs int32) ----------------------
__global__ void detect_kernel(const long long* __restrict__ ei) {
    if (threadIdx.x == 0) {
        int ok = 1;
        #pragma unroll 1
        for (int i = 0; i < 64; i++) {
            long long v = ei[i];
            if (v < 0 || v >= (long long)N_TOTAL) { ok = 0; break; }
        }
        g_is64 = ok;
    }
}

// ---------------- histogram of dst (reads only dst half of edge_index) -----
__global__ void count_kernel(const void* __restrict__ ei) {
    int i = blockIdx.x * blockDim.x + threadIdx.x;
    if (i >= E_EDGES) return;
    int t;
    if (g_is64) t = (int)((const long long*)ei)[E_EDGES + i];
    else        t = ((const int*)ei)[E_EDGES + i];
    atomicAdd(&g_cnt[t], 1);
}

// ---------------- 3-phase exclusive scan of g_cnt -> g_off -----------------
__global__ void __launch_bounds__(SCAN_CHUNK) scan1_kernel() {
    __shared__ int sm[SCAN_CHUNK];
    int t = threadIdx.x;
    int i = blockIdx.x * SCAN_CHUNK + t;
    int v = (i < N_TOTAL) ? g_cnt[i] : 0;
    sm[t] = v;
    __syncthreads();
    for (int d = 1; d < SCAN_CHUNK; d <<= 1) {
        int a = (t >= d) ? sm[t - d] : 0;
        __syncthreads();
        sm[t] += a;
        __syncthreads();
    }
    if (i < N_TOTAL) g_off[i] = sm[t] - v;       // exclusive
    if (t == SCAN_CHUNK - 1) g_bsum[blockIdx.x] = sm[t];
}

__global__ void scan2_kernel() {
    __shared__ int sm[256];
    int t = threadIdx.x;
    int v = (t < SCAN_NBLK) ? g_bsum[t] : 0;
    sm[t] = v;
    __syncthreads();
    for (int d = 1; d < 256; d <<= 1) {
        int a = (t >= d) ? sm[t - d] : 0;
        __syncthreads();
        sm[t] += a;
        __syncthreads();
    }
    if (t < SCAN_NBLK) g_bsum[t] = sm[t] - v;    // exclusive
}

__global__ void scan3_kernel() {
    int i = blockIdx.x * blockDim.x + threadIdx.x;
    if (i >= N_TOTAL) return;
    int o = g_off[i] + g_bsum[i >> 10];
    g_off[i] = o;
    g_cur[i] = o;
}

// ---------------- placement: dst-sorted edge list from raw inputs ----------
__global__ void place_kernel(const void* __restrict__ ei,
                             const float* __restrict__ w) {
    int i = blockIdx.x * blockDim.x + threadIdx.x;
    if (i >= E_EDGES) return;
    int s, t;
    if (g_is64) {
        const long long* p = (const long long*)ei;
        s = (int)p[i];
        t = (int)p[E_EDGES + i];
    } else {
        const int* p = (const int*)ei;
        s = p[i];
        t = p[E_EDGES + i];
    }
    int pos = atomicAdd(&g_cur[t], 1);
    g_esrt[pos] = make_int2(s, __float_as_int(w[i]));
}

// ---------------- build x = concat(user, item) -----------------------------
__global__ void init_x_kernel(const float4* __restrict__ ue,
                              const float4* __restrict__ ie) {
    int i = blockIdx.x * blockDim.x + threadIdx.x;
    const int total = N_TOTAL * DIM / 4;
    const int usplit = NUM_USERS * DIM / 4;
    if (i >= total) return;
    reinterpret_cast<float4*>(g_x)[i] = (i < usplit) ? ue[i] : ie[i - usplit];
}

// ---------------- segmented aggregation: out[n] = x[n] + sum w*x[src] ------
// One warp per dst node; float2 per lane covers the 64-wide row. Single base.
__global__ void __launch_bounds__(256) aggregate_kernel(
        const float* __restrict__ x, float* __restrict__ out) {
    int warp = (blockIdx.x * blockDim.x + threadIdx.x) >> 5;
    int lane = threadIdx.x & 31;
    if (warp >= N_TOTAL) return;

    int start = g_off[warp];
    int cnt   = g_cnt[warp];
    const float2* xp = reinterpret_cast<const float2*>(x);

    float2 acc = xp[(size_t)warp * 32 + lane];   // residual term

    int e = start, end = start + cnt;
    // 4-wide unrolled body for MLP: 4 independent gathers in flight.
    for (; e + 3 < end; e += 4) {
        int2 d0 = g_esrt[e];
        int2 d1 = g_esrt[e + 1];
        int2 d2 = g_esrt[e + 2];
        int2 d3 = g_esrt[e + 3];
        float2 v0 = xp[(size_t)d0.x * 32 + lane];
        float2 v1 = xp[(size_t)d1.x * 32 + lane];
        float2 v2 = xp[(size_t)d2.x * 32 + lane];
        float2 v3 = xp[(size_t)d3.x * 32 + lane];
        float w0 = __int_as_float(d0.y);
        float w1 = __int_as_float(d1.y);
        float w2 = __int_as_float(d2.y);
        float w3 = __int_as_float(d3.y);
        acc.x += w0 * v0.x + w1 * v1.x + w2 * v2.x + w3 * v3.x;
        acc.y += w0 * v0.y + w1 * v1.y + w2 * v2.y + w3 * v3.y;
    }
    for (; e < end; e++) {
        int2 d0 = g_esrt[e];
        float2 v0 = xp[(size_t)d0.x * 32 + lane];
        float w0 = __int_as_float(d0.y);
        acc.x += w0 * v0.x;
        acc.y += w0 * v0.y;
    }
    reinterpret_cast<float2*>(out)[(size_t)warp * 32 + lane] = acc;
}

// ---------------- linear: out = 0.5 * in @ W + b ---------------------------
// One row per warp (R2 structure), FFMA2 inner math.
// Smem W pre-paired: Ws2[j*64 + c] = {W[2j][c], W[2j+1][c]}.
__global__ void __launch_bounds__(256) linear_kernel(
        const float* __restrict__ in, const float* __restrict__ W,
        const float* __restrict__ b, float* __restrict__ out) {
    __shared__ ull Ws2[32 * 64];
    __shared__ float bs[DIM];
    for (int idx = threadIdx.x; idx < 32 * 64; idx += blockDim.x) {
        int j = idx >> 6, c = idx & 63;
        float2 p = make_float2(W[(2 * j) * DIM + c], W[(2 * j + 1) * DIM + c]);
        Ws2[idx] = *reinterpret_cast<ull*>(&p);
    }
    if (threadIdx.x < DIM) bs[threadIdx.x] = b[threadIdx.x];
    __syncthreads();

    int lane  = threadIdx.x & 31;
    int warp  = threadIdx.x >> 5;
    int nwpb  = blockDim.x >> 5;
    int stride = gridDim.x * nwpb;

    union F4U { float4 f; ull u[2]; };

    for (int row = blockIdx.x * nwpb + warp; row < N_TOTAL; row += stride) {
        const float4* rp = reinterpret_cast<const float4*>(in + (size_t)row * DIM);
        ull acc0 = 0, acc1 = 0;
        #pragma unroll
        for (int jj = 0; jj < 16; jj++) {       // float4 jj covers k = 4jj..4jj+3
            F4U v; v.f = rp[jj];                // broadcast within warp
            ull wA0 = Ws2[(2 * jj) * 64 + lane];        // pair {4jj, 4jj+1}
            ull wA1 = Ws2[(2 * jj) * 64 + 32 + lane];
            ull wB0 = Ws2[(2 * jj + 1) * 64 + lane];    // pair {4jj+2, 4jj+3}
            ull wB1 = Ws2[(2 * jj + 1) * 64 + 32 + lane];
            acc0 = ffma2(v.u[0], wA0, acc0);
            acc1 = ffma2(v.u[0], wA1, acc1);
            acc0 = ffma2(v.u[1], wB0, acc0);
            acc1 = ffma2(v.u[1], wB1, acc1);
        }
        float2 s0 = *reinterpret_cast<float2*>(&acc0);
        float2 s1 = *reinterpret_cast<float2*>(&acc1);
        size_t o = (size_t)row * DIM;
        out[o + lane]      = 0.5f * (s0.x + s0.y) + bs[lane];
        out[o + 32 + lane] = 0.5f * (s1.x + s1.y) + bs[32 + lane];
    }
}

// ---------------- launch ----------------------------------------------------
extern "C" void kernel_launch(void* const* d_in, const int* in_sizes, int n_in,
                              void* d_out, int out_size) {
    const void*  ei = d_in[0];
    const float* ew = (const float*)d_in[1];
    const float* ue = (const float*)d_in[2];
    const float* ie = (const float*)d_in[3];
    const float* W1 = (const float*)d_in[4];
    const float* b1 = (const float*)d_in[5];
    const float* W2 = (const float*)d_in[6];
    const float* b2 = (const float*)d_in[7];
    float* out = (float*)d_out;

    float *px, *pagg, *ph;
    int   *pcnt;
    cudaGetSymbolAddress((void**)&px,   g_x);
    cudaGetSymbolAddress((void**)&pagg, g_agg);
    cudaGetSymbolAddress((void**)&ph,   g_h);
    cudaGetSymbolAddress((void**)&pcnt, g_cnt);

    cudaMemsetAsync(pcnt, 0, N_TOTAL * sizeof(int));

    detect_kernel<<<1, 32>>>((const long long*)ei);

    count_kernel<<<(E_EDGES + 255) / 256, 256>>>(ei);

    scan1_kernel<<<SCAN_NBLK, SCAN_CHUNK>>>();
    scan2_kernel<<<1, 256>>>();
    scan3_kernel<<<(N_TOTAL + 255) / 256, 256>>>();

    place_kernel<<<(E_EDGES + 255) / 256, 256>>>(ei, ew);

    init_x_kernel<<<(N_TOTAL * DIM / 4 + 255) / 256, 256>>>(
        (const float4*)ue, (const float4*)ie);

    const int agg_blocks = (N_TOTAL * 32 + 255) / 256;   // 1 warp per node
    const int ln_blocks  = 2048;

    // Layer 1
    aggregate_kernel<<<agg_blocks, 256>>>(px, pagg);
    linear_kernel<<<ln_blocks, 256>>>(pagg, W1, b1, ph);

    // Layer 2
    aggregate_kernel<<<agg_blocks, 256>>>(ph, pagg);
    linear_kernel<<<ln_blocks, 256>>>(pagg, W2, b2, out);
}